// round 2
// baseline (speedup 1.0000x reference)
#include <cuda_runtime.h>
#include <math.h>

// Problem constants (fixed by the reference)
#define NN   10000
#define EE   160000
#define CC   16
#define HW   64
#define CHW  1024        // C*H*W
#define DE   64          // edge feature dim
#define HID  128         // hidden dim

// ---------------------------------------------------------------------------
// Scratch (no allocations allowed -> __device__ globals)
// ---------------------------------------------------------------------------
__device__ __align__(16) float g_flow_in [NN * CHW];   // 40.96 MB
__device__ __align__(16) float g_flow_out[NN * CHW];   // 40.96 MB
__device__ float g_sum_in [NN];
__device__ float g_sum_out[NN];
__device__ float g_exp[EE];
__device__ int   g_row[EE];
__device__ int   g_col[EE];
__device__ int   g_is64;

// ---------------------------------------------------------------------------
// Kernel 0a: detect whether edge_index is int64 or int32.
// int64 values < 2^32 have all-zero high words -> all odd int32 words zero.
// For genuine int32 random data P(first 64 odd words all zero) ~ 1e-256.
// ---------------------------------------------------------------------------
__global__ void detect_kernel(const int* __restrict__ v32) {
    int nz = 0;
#pragma unroll
    for (int q = 0; q < 4; q++) {
        int idx = 2 * (threadIdx.x + q * 32) + 1;   // odd words 1..255
        nz |= (v32[idx] != 0);
    }
#pragma unroll
    for (int s = 16; s > 0; s >>= 1)
        nz |= __shfl_xor_sync(0xffffffffu, nz, s);
    if (threadIdx.x == 0) g_is64 = nz ? 0 : 1;
}

// ---------------------------------------------------------------------------
// Kernel 0b: decode edge_index into int32 row/col arrays.
// ---------------------------------------------------------------------------
__global__ void decode_kernel(const int* __restrict__ v32) {
    int e = blockIdx.x * blockDim.x + threadIdx.x;
    if (e >= EE) return;
    int r, c;
    if (g_is64) {
        r = v32[2 * e];
        c = v32[2 * (EE + e)];
    } else {
        r = v32[e];
        c = v32[EE + e];
    }
    g_row[e] = r;
    g_col[e] = c;
}

// ---------------------------------------------------------------------------
// Kernel 1: zero the accumulators (graph is replayed -> must re-zero each call)
// ---------------------------------------------------------------------------
__global__ void zero_kernel() {
    int i = blockIdx.x * blockDim.x + threadIdx.x;
    float4 z = make_float4(0.f, 0.f, 0.f, 0.f);
    if (i < NN * CHW / 4) {
        reinterpret_cast<float4*>(g_flow_in)[i]  = z;
        reinterpret_cast<float4*>(g_flow_out)[i] = z;
    }
    if (i < NN) {
        g_sum_in[i]  = 0.f;
        g_sum_out[i] = 0.f;
    }
}

// ---------------------------------------------------------------------------
// Kernel 2: edge MLP -> logits, exp, and softmax denominators (fused)
//   h = relu(ea @ W1 + b1); logit = h @ W2 + b2
//   ex = exp(logit); atomicAdd to per-row sum (out: row<col, in: row>col)
// 128 threads, 256 edges per block (2 per thread, stride-128 so the
// eas[edge*65 + k] shared reads stay bank-conflict-free).
// ---------------------------------------------------------------------------
#define EPB 256
#define MLP_SMEM_FLOATS (8464 + EPB * 65)
#define MLP_SMEM_BYTES  (MLP_SMEM_FLOATS * 4)

extern __shared__ float smem[];

__global__ void mlp_kernel(const float* __restrict__ edge_attr,
                           const float* __restrict__ W1,
                           const float* __restrict__ b1,
                           const float* __restrict__ W2,
                           const float* __restrict__ b2,
                           float* __restrict__ logits,
                           int write_logits) {
    float* W1s = smem;              // [64][128] = 8192
    float* b1s = smem + 8192;       // 128
    float* W2s = smem + 8320;       // 128
    float* b2s = smem + 8448;       // 1 (padded region to 8464)
    float* eas = smem + 8464;       // [256][65]

    const int t = threadIdx.x;

    // Stage weights
    for (int i = t; i < 8192; i += 128) W1s[i] = W1[i];
    if (t < 128) { b1s[t] = b1[t]; W2s[t] = W2[t]; }
    if (t == 0)  b2s[0] = b2[0];

    // Stage 256 edges of edge_attr (coalesced float4 reads)
    const float4* ea4 = reinterpret_cast<const float4*>(
        edge_attr + (size_t)blockIdx.x * EPB * DE);
    for (int i = t; i < EPB * DE / 4; i += 128) {
        float4 v = ea4[i];
        int edge = i >> 4;          // 16 float4s per edge
        int k4   = i & 15;
        float* d = &eas[edge * 65 + k4 * 4];
        d[0] = v.x; d[1] = v.y; d[2] = v.z; d[3] = v.w;
    }
    __syncthreads();

    float logit0 = b2s[0];
    float logit1 = b2s[0];
    const float* ea0 = &eas[t * 65];
    const float* ea1 = &eas[(t + 128) * 65];

    for (int j0 = 0; j0 < HID; j0 += 16) {
        float acc0[16], acc1[16];
#pragma unroll
        for (int jj = 0; jj < 16; jj++) {
            float b = b1s[j0 + jj];
            acc0[jj] = b; acc1[jj] = b;
        }
#pragma unroll 4
        for (int k = 0; k < DE; k++) {
            float a0 = ea0[k];
            float a1 = ea1[k];
            const float4* w4 =
                reinterpret_cast<const float4*>(&W1s[k * HID + j0]);
#pragma unroll
            for (int m = 0; m < 4; m++) {
                float4 w = w4[m];   // broadcast LDS.128 (all lanes same addr)
                acc0[m*4+0] += a0 * w.x;  acc1[m*4+0] += a1 * w.x;
                acc0[m*4+1] += a0 * w.y;  acc1[m*4+1] += a1 * w.y;
                acc0[m*4+2] += a0 * w.z;  acc1[m*4+2] += a1 * w.z;
                acc0[m*4+3] += a0 * w.w;  acc1[m*4+3] += a1 * w.w;
            }
        }
#pragma unroll
        for (int jj = 0; jj < 16; jj++) {
            float w2 = W2s[j0 + jj];
            logit0 += fmaxf(acc0[jj], 0.f) * w2;
            logit1 += fmaxf(acc1[jj], 0.f) * w2;
        }
    }

    const int e0 = blockIdx.x * EPB + t;
    const int e1 = e0 + 128;

    {
        if (write_logits) logits[e0] = logit0;
        float ex = expf(logit0);
        g_exp[e0] = ex;
        int r = g_row[e0], c = g_col[e0];
        if (r < c)      atomicAdd(&g_sum_out[r], ex);
        else if (r > c) atomicAdd(&g_sum_in[r],  ex);
    }
    {
        if (write_logits) logits[e1] = logit1;
        float ex = expf(logit1);
        g_exp[e1] = ex;
        int r = g_row[e1], c = g_col[e1];
        if (r < c)      atomicAdd(&g_sum_out[r], ex);
        else if (r > c) atomicAdd(&g_sum_in[r],  ex);
    }
}

// ---------------------------------------------------------------------------
// Kernel 3: weighted message scatter. One block per edge, 256 threads.
// Addresses laid out so each warp's atomicAdd hits one contiguous 128B line.
// ---------------------------------------------------------------------------
__global__ void scatter_kernel(const float* __restrict__ x) {
    __shared__ float s_w;
    __shared__ int   s_row, s_col, s_dir;

    const int e = blockIdx.x;
    if (threadIdx.x == 0) {
        int r = g_row[e];
        int c = g_col[e];
        int dir = (r < c) ? 1 : ((r > c) ? 2 : 0);
        float w = 0.f;
        if (dir) {
            float sum = (dir == 1) ? g_sum_out[r] : g_sum_in[r];
            w = g_exp[e] / fmaxf(sum, 1e-30f);
        }
        s_row = r; s_col = c; s_dir = dir; s_w = w;
    }
    __syncthreads();

    const int dir = s_dir;
    if (!dir) return;                       // self-loop: masked in both flows

    const float w = s_w;
    const float* xs = x + (size_t)s_col * CHW;
    float* dst = ((dir == 1) ? g_flow_out : g_flow_in) + (size_t)s_row * CHW;

    const int t = threadIdx.x;
#pragma unroll
    for (int q = 0; q < 4; q++) {
        int idx = q * 256 + t;              // warp-contiguous addresses
        atomicAdd(&dst[idx], w * xs[idx]);
    }
}

// ---------------------------------------------------------------------------
// Kernel 4: 1x1 conv over concat([x, flow_in, flow_out]) + bias.
// 128 threads = 4 nodes/block, each thread handles 2 spatial positions.
// Wn staged transposed so coefficients load as broadcast LDS.128.
// ---------------------------------------------------------------------------
__global__ void conv_kernel(const float* __restrict__ x,
                            const float* __restrict__ Wn,
                            const float* __restrict__ bn,
                            float* __restrict__ out) {
    __shared__ float WsT[48 * 16];   // WsT[cat_c][o] = Wn[o][cat_c]
    __shared__ float bs[16];

    const int t = threadIdx.x;
    for (int i = t; i < 768; i += 128) {
        int o = i / 48, cc = i % 48;
        WsT[cc * 16 + o] = Wn[i];
    }
    if (t < 16) bs[t] = bn[t];
    __syncthreads();

    const int node = blockIdx.x * 4 + (t >> 5);
    const int hw   = t & 31;

    const float* xb = x          + (size_t)node * CHW;
    const float* fi = g_flow_in  + (size_t)node * CHW;
    const float* fo = g_flow_out + (size_t)node * CHW;

    float acc0[16], acc1[16];
#pragma unroll
    for (int o = 0; o < 16; o++) { acc0[o] = bs[o]; acc1[o] = bs[o]; }

#pragma unroll 4
    for (int c = 0; c < 16; c++) {
        float vx0 = xb[c * 64 + hw], vx1 = xb[c * 64 + hw + 32];
        float vi0 = fi[c * 64 + hw], vi1 = fi[c * 64 + hw + 32];
        float vo0 = fo[c * 64 + hw], vo1 = fo[c * 64 + hw + 32];
        const float4* wx = reinterpret_cast<const float4*>(&WsT[(c)      * 16]);
        const float4* wi = reinterpret_cast<const float4*>(&WsT[(16 + c) * 16]);
        const float4* wo = reinterpret_cast<const float4*>(&WsT[(32 + c) * 16]);
#pragma unroll
        for (int m = 0; m < 4; m++) {
            float4 a = wx[m], b = wi[m], d = wo[m];
            acc0[m*4+0] += vx0*a.x + vi0*b.x + vo0*d.x;
            acc1[m*4+0] += vx1*a.x + vi1*b.x + vo1*d.x;
            acc0[m*4+1] += vx0*a.y + vi0*b.y + vo0*d.y;
            acc1[m*4+1] += vx1*a.y + vi1*b.y + vo1*d.y;
            acc0[m*4+2] += vx0*a.z + vi0*b.z + vo0*d.z;
            acc1[m*4+2] += vx1*a.z + vi1*b.z + vo1*d.z;
            acc0[m*4+3] += vx0*a.w + vi0*b.w + vo0*d.w;
            acc1[m*4+3] += vx1*a.w + vi1*b.w + vo1*d.w;
        }
    }

    float* ob = out + (size_t)node * CHW;
#pragma unroll
    for (int o = 0; o < 16; o++) {
        ob[o * 64 + hw]      = acc0[o];
        ob[o * 64 + hw + 32] = acc1[o];
    }
}

// ---------------------------------------------------------------------------
// Launch: all on the default stream (sequentially ordered, graph-capturable)
// ---------------------------------------------------------------------------
extern "C" void kernel_launch(void* const* d_in, const int* in_sizes, int n_in,
                              void* d_out, int out_size) {
    const float* x         = (const float*)d_in[0];
    const float* edge_attr = (const float*)d_in[1];
    const float* W1        = (const float*)d_in[2];
    const float* b1        = (const float*)d_in[3];
    const float* W2        = (const float*)d_in[4];
    const float* b2        = (const float*)d_in[5];
    const float* Wn        = (const float*)d_in[6];
    const float* bn        = (const float*)d_in[7];
    const int*   ei32      = (const int*)d_in[8];    // int32 view; dtype probed

    float* out    = (float*)d_out;
    // dec_edge_feats appended after the conv output, if the harness expects it
    const int write_logits = (out_size >= NN * CHW + EE);
    float* logits = out + (size_t)NN * CHW;

    cudaFuncSetAttribute(mlp_kernel,
                         cudaFuncAttributeMaxDynamicSharedMemorySize,
                         MLP_SMEM_BYTES);

    detect_kernel<<<1, 32>>>(ei32);
    decode_kernel<<<(EE + 255) / 256, 256>>>(ei32);
    zero_kernel<<<(NN * CHW / 4 + 255) / 256, 256>>>();
    mlp_kernel<<<EE / EPB, 128, MLP_SMEM_BYTES>>>(edge_attr, W1, b1, W2, b2,
                                                  logits, write_logits);
    scatter_kernel<<<EE, 256>>>(x);
    conv_kernel<<<NN / 4, 128>>>(x, Wn, bn, out);
}

// round 3
// speedup vs baseline: 1.5242x; 1.5242x over previous
#include <cuda_runtime.h>
#include <math.h>

// Problem constants (fixed by the reference)
#define NN    10000
#define EE    160000
#define CC    16
#define CHW   1024       // C*H*W
#define DE    64         // edge feature dim
#define HID   128        // hidden dim
#define NSEG  (2 * NN)   // (node, dir) segments; dir 0 = out (r<c), 1 = in (r>c)

// ---------------------------------------------------------------------------
// Scratch (__device__ globals; no allocations allowed)
// ---------------------------------------------------------------------------
__device__ float g_sum_in [NN];
__device__ float g_sum_out[NN];
__device__ float g_exp[EE];
__device__ int   g_row[EE];
__device__ int   g_col[EE];
__device__ int   g_is64;
__device__ int   g_cnt[NSEG];
__device__ int   g_off[NSEG + 1];
__device__ int   g_pos[NSEG];
__device__ int   g_eid [EE];       // edge ids sorted by segment
__device__ int   g_scol[EE];       // col of sorted edge
__device__ float g_sw  [EE];       // softmax weight of sorted edge

// ---------------------------------------------------------------------------
// Kernel 0a: detect whether edge_index is int64 or int32.
// int64 values < 2^32 have all-zero high words -> all odd int32 words zero.
// ---------------------------------------------------------------------------
__global__ void detect_kernel(const int* __restrict__ v32) {
    int nz = 0;
#pragma unroll
    for (int q = 0; q < 4; q++) {
        int idx = 2 * (threadIdx.x + q * 32) + 1;
        nz |= (v32[idx] != 0);
    }
#pragma unroll
    for (int s = 16; s > 0; s >>= 1)
        nz |= __shfl_xor_sync(0xffffffffu, nz, s);
    if (threadIdx.x == 0) g_is64 = nz ? 0 : 1;
}

// ---------------------------------------------------------------------------
// Kernel 0b: decode edge_index into int32 row/col arrays.
// ---------------------------------------------------------------------------
__global__ void decode_kernel(const int* __restrict__ v32) {
    int e = blockIdx.x * blockDim.x + threadIdx.x;
    if (e >= EE) return;
    int r, c;
    if (g_is64) { r = v32[2 * e]; c = v32[2 * (EE + e)]; }
    else        { r = v32[e];     c = v32[EE + e]; }
    g_row[e] = r;
    g_col[e] = c;
}

// ---------------------------------------------------------------------------
// Kernel 1: zero the small accumulators (counters + softmax sums)
// ---------------------------------------------------------------------------
__global__ void zero_kernel() {
    int i = blockIdx.x * blockDim.x + threadIdx.x;
    if (i < NSEG) g_cnt[i] = 0;
    if (i < NN) { g_sum_in[i] = 0.f; g_sum_out[i] = 0.f; }
}

// ---------------------------------------------------------------------------
// CSR build: histogram -> scan -> fill
// ---------------------------------------------------------------------------
__global__ void hist_kernel() {
    int e = blockIdx.x * blockDim.x + threadIdx.x;
    if (e >= EE) return;
    int r = g_row[e], c = g_col[e];
    if (r == c) return;
    atomicAdd(&g_cnt[r * 2 + ((r < c) ? 0 : 1)], 1);
}

__global__ void scan_kernel() {   // single block, 1024 threads
    __shared__ int s[1024];
    __shared__ int carry;
    const int t = threadIdx.x;
    if (t == 0) carry = 0;
    __syncthreads();
    for (int base = 0; base < NSEG; base += 1024) {
        int idx = base + t;
        int v = (idx < NSEG) ? g_cnt[idx] : 0;
        s[t] = v;
        __syncthreads();
        for (int off = 1; off < 1024; off <<= 1) {
            int a = (t >= off) ? s[t - off] : 0;
            __syncthreads();
            s[t] += a;
            __syncthreads();
        }
        int excl = s[t] - v + carry;
        if (idx < NSEG) { g_off[idx] = excl; g_pos[idx] = excl; }
        __syncthreads();
        if (t == 1023) carry += s[1023];
        __syncthreads();
    }
    if (t == 0) g_off[NSEG] = carry;
}

__global__ void fill_kernel() {
    int e = blockIdx.x * blockDim.x + threadIdx.x;
    if (e >= EE) return;
    int r = g_row[e], c = g_col[e];
    if (r == c) return;
    int seg = r * 2 + ((r < c) ? 0 : 1);
    int pos = atomicAdd(&g_pos[seg], 1);
    g_eid[pos]  = e;
    g_scol[pos] = c;
}

// ---------------------------------------------------------------------------
// Kernel 2: edge MLP -> logits, exp, and softmax denominators (fused)
// 128 threads, 256 edges/block (2/thread), j-tile 32 (64 accumulators).
// ---------------------------------------------------------------------------
#define EPB 256
#define MLP_SMEM_FLOATS (8464 + EPB * 65)
#define MLP_SMEM_BYTES  (MLP_SMEM_FLOATS * 4)

extern __shared__ float smem[];

__global__ void __launch_bounds__(128)
mlp_kernel(const float* __restrict__ edge_attr,
           const float* __restrict__ W1,
           const float* __restrict__ b1,
           const float* __restrict__ W2,
           const float* __restrict__ b2,
           float* __restrict__ logits,
           int write_logits) {
    float* W1s = smem;              // [64][128]
    float* b1s = smem + 8192;       // 128
    float* W2s = smem + 8320;       // 128
    float* b2s = smem + 8448;       // 1
    float* eas = smem + 8464;       // [256][65]

    const int t = threadIdx.x;

    for (int i = t; i < 8192; i += 128) W1s[i] = W1[i];
    if (t < 128) { b1s[t] = b1[t]; W2s[t] = W2[t]; }
    if (t == 0)  b2s[0] = b2[0];

    const float4* ea4 = reinterpret_cast<const float4*>(
        edge_attr + (size_t)blockIdx.x * EPB * DE);
    for (int i = t; i < EPB * DE / 4; i += 128) {
        float4 v = ea4[i];
        int edge = i >> 4;
        int k4   = i & 15;
        float* d = &eas[edge * 65 + k4 * 4];
        d[0] = v.x; d[1] = v.y; d[2] = v.z; d[3] = v.w;
    }
    __syncthreads();

    float logit0 = b2s[0];
    float logit1 = b2s[0];
    const float* ea0 = &eas[t * 65];
    const float* ea1 = &eas[(t + 128) * 65];

#pragma unroll
    for (int j0 = 0; j0 < HID; j0 += 32) {
        float acc0[32], acc1[32];
#pragma unroll
        for (int jj = 0; jj < 32; jj++) {
            float b = b1s[j0 + jj];
            acc0[jj] = b; acc1[jj] = b;
        }
#pragma unroll 4
        for (int k = 0; k < DE; k++) {
            float a0 = ea0[k];
            float a1 = ea1[k];
            const float4* w4 =
                reinterpret_cast<const float4*>(&W1s[k * HID + j0]);
#pragma unroll
            for (int m = 0; m < 8; m++) {
                float4 w = w4[m];   // broadcast LDS.128
                acc0[m*4+0] += a0 * w.x;  acc1[m*4+0] += a1 * w.x;
                acc0[m*4+1] += a0 * w.y;  acc1[m*4+1] += a1 * w.y;
                acc0[m*4+2] += a0 * w.z;  acc1[m*4+2] += a1 * w.z;
                acc0[m*4+3] += a0 * w.w;  acc1[m*4+3] += a1 * w.w;
            }
        }
#pragma unroll
        for (int jj = 0; jj < 32; jj++) {
            float w2 = W2s[j0 + jj];
            logit0 += fmaxf(acc0[jj], 0.f) * w2;
            logit1 += fmaxf(acc1[jj], 0.f) * w2;
        }
    }

    const int e0 = blockIdx.x * EPB + t;
    const int e1 = e0 + 128;
    {
        if (write_logits) logits[e0] = logit0;
        float ex = expf(logit0);
        g_exp[e0] = ex;
        int r = g_row[e0], c = g_col[e0];
        if (r < c)      atomicAdd(&g_sum_out[r], ex);
        else if (r > c) atomicAdd(&g_sum_in[r],  ex);
    }
    {
        if (write_logits) logits[e1] = logit1;
        float ex = expf(logit1);
        g_exp[e1] = ex;
        int r = g_row[e1], c = g_col[e1];
        if (r < c)      atomicAdd(&g_sum_out[r], ex);
        else if (r > c) atomicAdd(&g_sum_in[r],  ex);
    }
}

// ---------------------------------------------------------------------------
// Kernel 3: per sorted edge, final softmax weight (needs sums from MLP)
// ---------------------------------------------------------------------------
__global__ void weight_kernel() {
    int pos = blockIdx.x * blockDim.x + threadIdx.x;
    if (pos >= g_off[NSEG]) return;
    int e = g_eid[pos];
    int r = g_row[e], c = g_col[e];
    float sum = (r < c) ? g_sum_out[r] : g_sum_in[r];
    g_sw[pos] = g_exp[e] / fmaxf(sum, 1e-30f);
}

// ---------------------------------------------------------------------------
// Kernel 4: fused gather-aggregate + 1x1 conv. One block per node,
// 256 threads; each thread owns one float4 of the 1024-float node tile.
// No atomics, flow never leaves the SM.
// ---------------------------------------------------------------------------
__global__ void __launch_bounds__(256)
fused_kernel(const float* __restrict__ x,
             const float* __restrict__ Wn,
             const float* __restrict__ bn,
             float* __restrict__ out) {
    __shared__ float s_fo[CHW];      // flow_out
    __shared__ float s_fi[CHW];      // flow_in
    __shared__ float WsT[48 * 16];   // WsT[cc][o] = Wn[o*48+cc]
    __shared__ float bs[16];

    const int n = blockIdx.x;
    const int t = threadIdx.x;

    // Stage conv weights (overlaps with edge gathering below)
    for (int i = t; i < 768; i += 256) {
        int o = i / 48, cc = i % 48;
        WsT[cc * 16 + o] = Wn[i];
    }
    if (t < 16) bs[t] = bn[t];

    const int off0 = g_off[2 * n];
    const int off1 = g_off[2 * n + 1];
    const int off2 = g_off[2 * n + 2];

    const float4* x4 = reinterpret_cast<const float4*>(x);

    float4 accO = make_float4(0.f, 0.f, 0.f, 0.f);
    float4 accI = make_float4(0.f, 0.f, 0.f, 0.f);

    // software-pipelined edge walk: prefetch next (col, w)
    int   col_n = 0;
    float w_n   = 0.f;
    if (off0 < off2) { col_n = g_scol[off0]; w_n = g_sw[off0]; }
    for (int i = off0; i < off2; i++) {
        int   col = col_n;
        float w   = w_n;
        if (i + 1 < off2) { col_n = g_scol[i + 1]; w_n = g_sw[i + 1]; }
        float4 xv = __ldg(&x4[(size_t)col * 256 + t]);
        if (i < off1) {
            accO.x += w * xv.x; accO.y += w * xv.y;
            accO.z += w * xv.z; accO.w += w * xv.w;
        } else {
            accI.x += w * xv.x; accI.y += w * xv.y;
            accI.z += w * xv.z; accI.w += w * xv.w;
        }
    }

    reinterpret_cast<float4*>(s_fo)[t] = accO;
    reinterpret_cast<float4*>(s_fi)[t] = accI;
    __syncthreads();

    // Conv: thread -> (og = t/64 -> outputs og*4..og*4+3, hw = t%64)
    const int hw = t & 63;
    const int og = t >> 6;

    float acc[4];
#pragma unroll
    for (int j = 0; j < 4; j++) acc[j] = bs[og * 4 + j];

    const float* xb = x + (size_t)n * CHW;
#pragma unroll 4
    for (int cc = 0; cc < 16; cc++) {
        float vx = __ldg(&xb[cc * 64 + hw]);
        float vi = s_fi[cc * 64 + hw];
        float vo = s_fo[cc * 64 + hw];
        float4 wx = reinterpret_cast<const float4*>(&WsT[(cc)      * 16])[og];
        float4 wi = reinterpret_cast<const float4*>(&WsT[(16 + cc) * 16])[og];
        float4 wo = reinterpret_cast<const float4*>(&WsT[(32 + cc) * 16])[og];
        acc[0] += vx * wx.x + vi * wi.x + vo * wo.x;
        acc[1] += vx * wx.y + vi * wi.y + vo * wo.y;
        acc[2] += vx * wx.z + vi * wi.z + vo * wo.z;
        acc[3] += vx * wx.w + vi * wi.w + vo * wo.w;
    }

    float* ob = out + (size_t)n * CHW;
#pragma unroll
    for (int j = 0; j < 4; j++)
        ob[(og * 4 + j) * 64 + hw] = acc[j];
}

// ---------------------------------------------------------------------------
// Launch (default stream; sequentially ordered; graph-capturable)
// ---------------------------------------------------------------------------
extern "C" void kernel_launch(void* const* d_in, const int* in_sizes, int n_in,
                              void* d_out, int out_size) {
    const float* x         = (const float*)d_in[0];
    const float* edge_attr = (const float*)d_in[1];
    const float* W1        = (const float*)d_in[2];
    const float* b1        = (const float*)d_in[3];
    const float* W2        = (const float*)d_in[4];
    const float* b2        = (const float*)d_in[5];
    const float* Wn        = (const float*)d_in[6];
    const float* bn        = (const float*)d_in[7];
    const int*   ei32      = (const int*)d_in[8];

    float* out    = (float*)d_out;
    const int write_logits = (out_size >= NN * CHW + EE);
    float* logits = out + (size_t)NN * CHW;

    cudaFuncSetAttribute(mlp_kernel,
                         cudaFuncAttributeMaxDynamicSharedMemorySize,
                         MLP_SMEM_BYTES);

    const int EB = (EE + 255) / 256;

    detect_kernel<<<1, 32>>>(ei32);
    decode_kernel<<<EB, 256>>>(ei32);
    zero_kernel<<<(NSEG + 255) / 256, 256>>>();
    hist_kernel<<<EB, 256>>>();
    scan_kernel<<<1, 1024>>>();
    fill_kernel<<<EB, 256>>>();
    mlp_kernel<<<EE / EPB, 128, MLP_SMEM_BYTES>>>(edge_attr, W1, b1, W2, b2,
                                                  logits, write_logits);
    weight_kernel<<<EB, 256>>>();
    fused_kernel<<<NN, 256>>>(x, Wn, bn, out);
}

// round 4
// speedup vs baseline: 1.9077x; 1.2516x over previous
#include <cuda_runtime.h>
#include <math.h>

// Problem constants (fixed by the reference)
#define NN    10000
#define EE    160000
#define CC    16
#define CHW   1024       // C*H*W
#define DE    64         // edge feature dim
#define HID   128        // hidden dim
#define NSEG  (2 * NN)   // (node, dir) segments; dir 0 = out (r<c), 1 = in (r>c)

// ---------------------------------------------------------------------------
// Scratch (__device__ globals; no allocations allowed)
// ---------------------------------------------------------------------------
__device__ float g_sum_in [NN];
__device__ float g_sum_out[NN];
__device__ float g_exp[EE];
__device__ int   g_row[EE];
__device__ int   g_col[EE];
__device__ int   g_is64;
__device__ int   g_cnt[NSEG];
__device__ int   g_off[NSEG + 1];
__device__ int   g_pos[NSEG];
__device__ int   g_eid [EE];       // edge ids sorted by segment
__device__ int   g_scol[EE];       // col of sorted edge

// ---------------------------------------------------------------------------
// f32x2 packed helpers (sm_100+): 2 fp32 FMAs per issue slot.
// Plain 3-reg FFMA is half-rate (rt_SMSP=2); FFMA2 doubles the fp32 ceiling.
// ---------------------------------------------------------------------------
__device__ __forceinline__ unsigned long long ffma2(unsigned long long a,
                                                    unsigned long long b,
                                                    unsigned long long c) {
    unsigned long long d;
    asm("fma.rn.f32x2 %0, %1, %2, %3;" : "=l"(d) : "l"(a), "l"(b), "l"(c));
    return d;
}
__device__ __forceinline__ unsigned long long pack2(float a) {
    unsigned long long r;
    unsigned int u = __float_as_uint(a);
    asm("mov.b64 %0, {%1, %1};" : "=l"(r) : "r"(u));
    return r;
}
union U64F2 { unsigned long long u; float2 f; };

// ---------------------------------------------------------------------------
// Kernel 0a: detect whether edge_index is int64 or int32.
// int64 values < 2^32 have all-zero high words -> all odd int32 words zero.
// ---------------------------------------------------------------------------
__global__ void detect_kernel(const int* __restrict__ v32) {
    int nz = 0;
#pragma unroll
    for (int q = 0; q < 4; q++) {
        int idx = 2 * (threadIdx.x + q * 32) + 1;
        nz |= (v32[idx] != 0);
    }
#pragma unroll
    for (int s = 16; s > 0; s >>= 1)
        nz |= __shfl_xor_sync(0xffffffffu, nz, s);
    if (threadIdx.x == 0) g_is64 = nz ? 0 : 1;
}

// ---------------------------------------------------------------------------
// Kernel 1: zero the small accumulators (counters + softmax sums)
// ---------------------------------------------------------------------------
__global__ void zero_kernel() {
    int i = blockIdx.x * blockDim.x + threadIdx.x;
    if (i < NSEG) g_cnt[i] = 0;
    if (i < NN) { g_sum_in[i] = 0.f; g_sum_out[i] = 0.f; }
}

// ---------------------------------------------------------------------------
// Kernel 2: decode edge_index + segment histogram (merged)
// ---------------------------------------------------------------------------
__global__ void decode_kernel(const int* __restrict__ v32) {
    int e = blockIdx.x * blockDim.x + threadIdx.x;
    if (e >= EE) return;
    int r, c;
    if (g_is64) { r = v32[2 * e]; c = v32[2 * (EE + e)]; }
    else        { r = v32[e];     c = v32[EE + e]; }
    g_row[e] = r;
    g_col[e] = c;
    if (r != c) atomicAdd(&g_cnt[r * 2 + ((r < c) ? 0 : 1)], 1);
}

// ---------------------------------------------------------------------------
// Kernel 3: exclusive scan of g_cnt (single block, warp-shuffle based)
// ---------------------------------------------------------------------------
__global__ void scan_kernel() {
    __shared__ int wsum[32];
    __shared__ int carry;
    const int t    = threadIdx.x;
    const int lane = t & 31;
    const int wid  = t >> 5;
    if (t == 0) carry = 0;
    __syncthreads();
    for (int base = 0; base < NSEG; base += 1024) {
        int idx = base + t;
        int v = (idx < NSEG) ? g_cnt[idx] : 0;
        int s = v;
#pragma unroll
        for (int off = 1; off < 32; off <<= 1) {
            int n = __shfl_up_sync(0xffffffffu, s, off);
            if (lane >= off) s += n;
        }
        if (lane == 31) wsum[wid] = s;
        __syncthreads();
        if (wid == 0) {
            int w = wsum[lane];
#pragma unroll
            for (int off = 1; off < 32; off <<= 1) {
                int n = __shfl_up_sync(0xffffffffu, w, off);
                if (lane >= off) w += n;
            }
            wsum[lane] = w;
        }
        __syncthreads();
        int incl = s + ((wid > 0) ? wsum[wid - 1] : 0);
        int excl = incl - v + carry;
        if (idx < NSEG) { g_off[idx] = excl; g_pos[idx] = excl; }
        __syncthreads();
        if (t == 1023) carry += incl;
        __syncthreads();
    }
    if (t == 0) g_off[NSEG] = carry;
}

// ---------------------------------------------------------------------------
// Kernel 4: fill CSR lists
// ---------------------------------------------------------------------------
__global__ void fill_kernel() {
    int e = blockIdx.x * blockDim.x + threadIdx.x;
    if (e >= EE) return;
    int r = g_row[e], c = g_col[e];
    if (r == c) return;
    int seg = r * 2 + ((r < c) ? 0 : 1);
    int pos = atomicAdd(&g_pos[seg], 1);
    g_eid[pos]  = e;
    g_scol[pos] = c;
}

// ---------------------------------------------------------------------------
// Kernel 5: edge MLP (f32x2 packed) -> logits, exp, softmax denominators
// 128 threads, 256 edges/block (2/thread), j-tile 32 (16 packed acc pairs/edge)
// ---------------------------------------------------------------------------
#define EPB 256
#define MLP_SMEM_FLOATS (8464 + EPB * 65)
#define MLP_SMEM_BYTES  (MLP_SMEM_FLOATS * 4)

extern __shared__ float smem[];

__global__ void __launch_bounds__(128)
mlp_kernel(const float* __restrict__ edge_attr,
           const float* __restrict__ W1,
           const float* __restrict__ b1,
           const float* __restrict__ W2,
           const float* __restrict__ b2,
           float* __restrict__ logits,
           int write_logits) {
    float* W1s = smem;              // [64][128]
    float* b1s = smem + 8192;       // 128
    float* W2s = smem + 8320;       // 128
    float* b2s = smem + 8448;       // 1
    float* eas = smem + 8464;       // [256][65]

    const int t = threadIdx.x;

    for (int i = t; i < 8192; i += 128) W1s[i] = W1[i];
    if (t < 128) { b1s[t] = b1[t]; W2s[t] = W2[t]; }
    if (t == 0)  b2s[0] = b2[0];

    const float4* ea4 = reinterpret_cast<const float4*>(
        edge_attr + (size_t)blockIdx.x * EPB * DE);
    for (int i = t; i < EPB * DE / 4; i += 128) {
        float4 v = ea4[i];
        int edge = i >> 4;
        int k4   = i & 15;
        float* d = &eas[edge * 65 + k4 * 4];
        d[0] = v.x; d[1] = v.y; d[2] = v.z; d[3] = v.w;
    }
    __syncthreads();

    float logit0 = b2s[0];
    float logit1 = b2s[0];
    const float* ea0 = &eas[t * 65];
    const float* ea1 = &eas[(t + 128) * 65];

#pragma unroll
    for (int j0 = 0; j0 < HID; j0 += 32) {
        unsigned long long acc0[16], acc1[16];
        const unsigned long long* b1p =
            reinterpret_cast<const unsigned long long*>(&b1s[j0]);
#pragma unroll
        for (int m = 0; m < 16; m++) { acc0[m] = b1p[m]; acc1[m] = b1p[m]; }

#pragma unroll 4
        for (int k = 0; k < DE; k++) {
            unsigned long long A0 = pack2(ea0[k]);
            unsigned long long A1 = pack2(ea1[k]);
            const ulonglong2* w2 =
                reinterpret_cast<const ulonglong2*>(&W1s[k * HID + j0]);
#pragma unroll
            for (int m = 0; m < 8; m++) {
                ulonglong2 w = w2[m];   // broadcast LDS.128 (2 f32x2 pairs)
                acc0[2*m]   = ffma2(A0, w.x, acc0[2*m]);
                acc0[2*m+1] = ffma2(A0, w.y, acc0[2*m+1]);
                acc1[2*m]   = ffma2(A1, w.x, acc1[2*m]);
                acc1[2*m+1] = ffma2(A1, w.y, acc1[2*m+1]);
            }
        }
#pragma unroll
        for (int m = 0; m < 16; m++) {
            U64F2 c0; c0.u = acc0[m];
            U64F2 c1; c1.u = acc1[m];
            float w2a = W2s[j0 + 2*m];
            float w2b = W2s[j0 + 2*m + 1];
            logit0 += fmaxf(c0.f.x, 0.f) * w2a + fmaxf(c0.f.y, 0.f) * w2b;
            logit1 += fmaxf(c1.f.x, 0.f) * w2a + fmaxf(c1.f.y, 0.f) * w2b;
        }
    }

    const int e0 = blockIdx.x * EPB + t;
    const int e1 = e0 + 128;
    {
        if (write_logits) logits[e0] = logit0;
        float ex = expf(logit0);
        g_exp[e0] = ex;
        int r = g_row[e0], c = g_col[e0];
        if (r < c)      atomicAdd(&g_sum_out[r], ex);
        else if (r > c) atomicAdd(&g_sum_in[r],  ex);
    }
    {
        if (write_logits) logits[e1] = logit1;
        float ex = expf(logit1);
        g_exp[e1] = ex;
        int r = g_row[e1], c = g_col[e1];
        if (r < c)      atomicAdd(&g_sum_out[r], ex);
        else if (r > c) atomicAdd(&g_sum_in[r],  ex);
    }
}

// ---------------------------------------------------------------------------
// Kernel 6: fused gather-aggregate + 1x1 conv. One block per node,
// 256 threads; each thread owns one float4 of the node tile. No atomics;
// softmax weights computed in-block (chunk-staged into smem).
// ---------------------------------------------------------------------------
#define ECHUNK 128

__global__ void __launch_bounds__(256)
fused_kernel(const float* __restrict__ x,
             const float* __restrict__ Wn,
             const float* __restrict__ bn,
             float* __restrict__ out) {
    __shared__ float s_fo[CHW];      // flow_out
    __shared__ float s_fi[CHW];      // flow_in
    __shared__ float WsT[48 * 16];   // WsT[cc][o] = Wn[o*48+cc]
    __shared__ float bs[16];
    __shared__ int   s_ec[ECHUNK];
    __shared__ float s_ew[ECHUNK];

    const int n = blockIdx.x;
    const int t = threadIdx.x;

    // Stage conv weights (overlaps with edge gathering)
    for (int i = t; i < 768; i += 256) {
        int o = i / 48, cc = i % 48;
        WsT[cc * 16 + o] = Wn[i];
    }
    if (t < 16) bs[t] = bn[t];

    const int off0 = g_off[2 * n];
    const int off1 = g_off[2 * n + 1];
    const int off2 = g_off[2 * n + 2];

    const float invO = 1.f / fmaxf(g_sum_out[n], 1e-30f);
    const float invI = 1.f / fmaxf(g_sum_in[n],  1e-30f);

    const float4* x4 = reinterpret_cast<const float4*>(x);

    float4 accO = make_float4(0.f, 0.f, 0.f, 0.f);
    float4 accI = make_float4(0.f, 0.f, 0.f, 0.f);

    // dir 0: outgoing flow (r < c)
    for (int base = off0; base < off1; base += ECHUNK) {
        int m = min(ECHUNK, off1 - base);
        __syncthreads();
        for (int j = t; j < m; j += 256) {
            s_ec[j] = g_scol[base + j];
            s_ew[j] = g_exp[g_eid[base + j]] * invO;
        }
        __syncthreads();
#pragma unroll 2
        for (int j = 0; j < m; j++) {
            float w = s_ew[j];
            float4 xv = __ldg(&x4[(size_t)s_ec[j] * 256 + t]);
            accO.x += w * xv.x; accO.y += w * xv.y;
            accO.z += w * xv.z; accO.w += w * xv.w;
        }
    }
    // dir 1: incoming flow (r > c)
    for (int base = off1; base < off2; base += ECHUNK) {
        int m = min(ECHUNK, off2 - base);
        __syncthreads();
        for (int j = t; j < m; j += 256) {
            s_ec[j] = g_scol[base + j];
            s_ew[j] = g_exp[g_eid[base + j]] * invI;
        }
        __syncthreads();
#pragma unroll 2
        for (int j = 0; j < m; j++) {
            float w = s_ew[j];
            float4 xv = __ldg(&x4[(size_t)s_ec[j] * 256 + t]);
            accI.x += w * xv.x; accI.y += w * xv.y;
            accI.z += w * xv.z; accI.w += w * xv.w;
        }
    }

    __syncthreads();   // staging buffers done; also orders Wn/bs staging
    reinterpret_cast<float4*>(s_fo)[t] = accO;
    reinterpret_cast<float4*>(s_fi)[t] = accI;
    __syncthreads();

    // Conv: thread -> (og = t/64 -> outputs og*4..og*4+3, hw = t%64)
    const int hw = t & 63;
    const int og = t >> 6;

    float acc[4];
#pragma unroll
    for (int j = 0; j < 4; j++) acc[j] = bs[og * 4 + j];

    const float* xb = x + (size_t)n * CHW;
#pragma unroll 4
    for (int cc = 0; cc < 16; cc++) {
        float vx = __ldg(&xb[cc * 64 + hw]);
        float vi = s_fi[cc * 64 + hw];
        float vo = s_fo[cc * 64 + hw];
        float4 wx = reinterpret_cast<const float4*>(&WsT[(cc)      * 16])[og];
        float4 wi = reinterpret_cast<const float4*>(&WsT[(16 + cc) * 16])[og];
        float4 wo = reinterpret_cast<const float4*>(&WsT[(32 + cc) * 16])[og];
        acc[0] += vx * wx.x + vi * wi.x + vo * wo.x;
        acc[1] += vx * wx.y + vi * wi.y + vo * wo.y;
        acc[2] += vx * wx.z + vi * wi.z + vo * wo.z;
        acc[3] += vx * wx.w + vi * wi.w + vo * wo.w;
    }

    float* ob = out + (size_t)n * CHW;
#pragma unroll
    for (int j = 0; j < 4; j++)
        ob[(og * 4 + j) * 64 + hw] = acc[j];
}

// ---------------------------------------------------------------------------
// Launch (default stream; sequentially ordered; graph-capturable)
// ---------------------------------------------------------------------------
extern "C" void kernel_launch(void* const* d_in, const int* in_sizes, int n_in,
                              void* d_out, int out_size) {
    const float* x         = (const float*)d_in[0];
    const float* edge_attr = (const float*)d_in[1];
    const float* W1        = (const float*)d_in[2];
    const float* b1        = (const float*)d_in[3];
    const float* W2        = (const float*)d_in[4];
    const float* b2        = (const float*)d_in[5];
    const float* Wn        = (const float*)d_in[6];
    const float* bn        = (const float*)d_in[7];
    const int*   ei32      = (const int*)d_in[8];

    float* out    = (float*)d_out;
    const int write_logits = (out_size >= NN * CHW + EE);
    float* logits = out + (size_t)NN * CHW;

    cudaFuncSetAttribute(mlp_kernel,
                         cudaFuncAttributeMaxDynamicSharedMemorySize,
                         MLP_SMEM_BYTES);

    const int EB = (EE + 255) / 256;

    detect_kernel<<<1, 32>>>(ei32);
    zero_kernel<<<(NSEG + 255) / 256, 256>>>();
    decode_kernel<<<EB, 256>>>(ei32);
    scan_kernel<<<1, 1024>>>();
    fill_kernel<<<EB, 256>>>();
    mlp_kernel<<<EE / EPB, 128, MLP_SMEM_BYTES>>>(edge_attr, W1, b1, W2, b2,
                                                  logits, write_logits);
    fused_kernel<<<NN, 256>>>(x, Wn, bn, out);
}

// round 5
// speedup vs baseline: 2.0034x; 1.0502x over previous
#include <cuda_runtime.h>
#include <math.h>

// Problem constants (fixed by the reference)
#define NN    10000
#define EE    160000
#define CC    16
#define CHW   1024       // C*H*W
#define DE    64         // edge feature dim
#define HID   128        // hidden dim
#define NSEG  (2 * NN)   // (node, dir) segments; dir 0 = out (r<c), 1 = in (r>c)
#define NSCANB ((NSEG + 1023) / 1024)   // 20 scan blocks

// ---------------------------------------------------------------------------
// Scratch (__device__ globals; no allocations allowed)
// ---------------------------------------------------------------------------
__device__ float g_sum_in [NN];
__device__ float g_sum_out[NN];
__device__ float g_exp[EE];
__device__ int   g_row[EE];
__device__ int   g_col[EE];
__device__ int   g_is64;
__device__ int   g_cnt[NSEG];
__device__ int   g_off[NSEG + 1];
__device__ int   g_pos[NSEG];
__device__ int   g_bsum[NSCANB];
__device__ int   g_eid [EE];       // edge ids sorted by segment
__device__ int   g_scol[EE];       // col of sorted edge

// ---------------------------------------------------------------------------
// f32x2 packed helpers (sm_100+): 2 fp32 FMAs per issue slot.
// ---------------------------------------------------------------------------
__device__ __forceinline__ unsigned long long ffma2(unsigned long long a,
                                                    unsigned long long b,
                                                    unsigned long long c) {
    unsigned long long d;
    asm("fma.rn.f32x2 %0, %1, %2, %3;" : "=l"(d) : "l"(a), "l"(b), "l"(c));
    return d;
}
__device__ __forceinline__ unsigned long long pack2(float a) {
    unsigned long long r;
    unsigned int u = __float_as_uint(a);
    asm("mov.b64 %0, {%1, %1};" : "=l"(r) : "r"(u));
    return r;
}
union U64F2 { unsigned long long u; float2 f; };

// ---------------------------------------------------------------------------
// Kernel 1: zero accumulators + (block 0) detect int64 vs int32 edge_index.
// int64 values < 2^32 have all-zero high words -> all odd int32 words zero.
// ---------------------------------------------------------------------------
__global__ void zero_kernel(const int* __restrict__ v32) {
    int i = blockIdx.x * blockDim.x + threadIdx.x;
    if (i < NSEG) g_cnt[i] = 0;
    if (i < NN) { g_sum_in[i] = 0.f; g_sum_out[i] = 0.f; }
    if (blockIdx.x == 0 && threadIdx.x < 32) {
        int t = threadIdx.x;
        int nz = 0;
#pragma unroll
        for (int q = 0; q < 4; q++)
            nz |= (v32[2 * (t + q * 32) + 1] != 0);
#pragma unroll
        for (int s = 16; s > 0; s >>= 1)
            nz |= __shfl_xor_sync(0xffffffffu, nz, s);
        if (t == 0) g_is64 = nz ? 0 : 1;
    }
}

// ---------------------------------------------------------------------------
// Kernel 2: decode edge_index + segment histogram (merged)
// ---------------------------------------------------------------------------
__global__ void decode_kernel(const int* __restrict__ v32) {
    int e = blockIdx.x * blockDim.x + threadIdx.x;
    if (e >= EE) return;
    int r, c;
    if (g_is64) { r = v32[2 * e]; c = v32[2 * (EE + e)]; }
    else        { r = v32[e];     c = v32[EE + e]; }
    g_row[e] = r;
    g_col[e] = c;
    if (r != c) atomicAdd(&g_cnt[r * 2 + ((r < c) ? 0 : 1)], 1);
}

// ---------------------------------------------------------------------------
// Kernels 3a/3b/3c: multi-block exclusive scan of g_cnt
// ---------------------------------------------------------------------------
__global__ void scanA_kernel() {      // NSCANB blocks x 1024
    __shared__ int wsum[32];
    const int t = threadIdx.x, lane = t & 31, wid = t >> 5;
    const int idx = blockIdx.x * 1024 + t;
    int v = (idx < NSEG) ? g_cnt[idx] : 0;
    int s = v;
#pragma unroll
    for (int off = 1; off < 32; off <<= 1) {
        int n = __shfl_up_sync(0xffffffffu, s, off);
        if (lane >= off) s += n;
    }
    if (lane == 31) wsum[wid] = s;
    __syncthreads();
    if (wid == 0) {
        int w = wsum[lane];
#pragma unroll
        for (int off = 1; off < 32; off <<= 1) {
            int n = __shfl_up_sync(0xffffffffu, w, off);
            if (lane >= off) w += n;
        }
        wsum[lane] = w;
    }
    __syncthreads();
    int incl = s + ((wid > 0) ? wsum[wid - 1] : 0);
    if (idx < NSEG) g_off[idx] = incl - v;       // local exclusive
    if (t == 1023) g_bsum[blockIdx.x] = incl;    // block total
}

__global__ void scanB_kernel() {      // 1 block x 32
    const int lane = threadIdx.x;
    int v = (lane < NSCANB) ? g_bsum[lane] : 0;
    int s = v;
#pragma unroll
    for (int off = 1; off < 32; off <<= 1) {
        int n = __shfl_up_sync(0xffffffffu, s, off);
        if (lane >= off) s += n;
    }
    if (lane < NSCANB) g_bsum[lane] = s - v;     // exclusive
    if (lane == 31) g_off[NSEG] = s;             // grand total
}

__global__ void scanC_kernel() {      // apply block offsets
    int idx = blockIdx.x * blockDim.x + threadIdx.x;
    if (idx >= NSEG) return;
    int o = g_off[idx] + g_bsum[idx >> 10];
    g_off[idx] = o;
    g_pos[idx] = o;
}

// ---------------------------------------------------------------------------
// Kernel 4: fill CSR lists
// ---------------------------------------------------------------------------
__global__ void fill_kernel() {
    int e = blockIdx.x * blockDim.x + threadIdx.x;
    if (e >= EE) return;
    int r = g_row[e], c = g_col[e];
    if (r == c) return;
    int seg = r * 2 + ((r < c) ? 0 : 1);
    int pos = atomicAdd(&g_pos[seg], 1);
    g_eid[pos]  = e;
    g_scol[pos] = c;
}

// ---------------------------------------------------------------------------
// Kernel 5: edge MLP (f32x2 packed) -> logits, exp, softmax denominators
// 128 threads, 256 edges/block (2/thread), j-tile 32.
// edge_attr staged with stride 68 (16B aligned) so per-thread reads are
// conflict-free LDS.128.
// ---------------------------------------------------------------------------
#define EPB 256
#define EA_STRIDE 68
#define MLP_SMEM_FLOATS (8464 + EPB * EA_STRIDE)
#define MLP_SMEM_BYTES  (MLP_SMEM_FLOATS * 4)

extern __shared__ float smem[];

__global__ void __launch_bounds__(128)
mlp_kernel(const float* __restrict__ edge_attr,
           const float* __restrict__ W1,
           const float* __restrict__ b1,
           const float* __restrict__ W2,
           const float* __restrict__ b2,
           float* __restrict__ logits,
           int write_logits) {
    float* W1s = smem;              // [64][128]
    float* b1s = smem + 8192;       // 128
    float* W2s = smem + 8320;       // 128
    float* b2s = smem + 8448;       // 1 (pad to 8464 for 16B alignment)
    float* eas = smem + 8464;       // [256][68]

    const int t = threadIdx.x;

    for (int i = t; i < 8192; i += 128) W1s[i] = W1[i];
    if (t < 128) { b1s[t] = b1[t]; W2s[t] = W2[t]; }
    if (t == 0)  b2s[0] = b2[0];

    const float4* ea4 = reinterpret_cast<const float4*>(
        edge_attr + (size_t)blockIdx.x * EPB * DE);
    for (int i = t; i < EPB * DE / 4; i += 128) {
        float4 v = ea4[i];
        int edge = i >> 4;
        int k4   = i & 15;
        reinterpret_cast<float4*>(&eas[edge * EA_STRIDE])[k4] = v;
    }
    __syncthreads();

    float logit0 = b2s[0];
    float logit1 = b2s[0];
    const float4* ea0 = reinterpret_cast<const float4*>(&eas[t * EA_STRIDE]);
    const float4* ea1 = reinterpret_cast<const float4*>(
        &eas[(t + 128) * EA_STRIDE]);

#pragma unroll
    for (int j0 = 0; j0 < HID; j0 += 32) {
        unsigned long long acc0[16], acc1[16];
        const unsigned long long* b1p =
            reinterpret_cast<const unsigned long long*>(&b1s[j0]);
#pragma unroll
        for (int m = 0; m < 16; m++) { acc0[m] = b1p[m]; acc1[m] = b1p[m]; }

#pragma unroll 2
        for (int k4 = 0; k4 < 16; k4++) {
            float4 a0 = ea0[k4];          // LDS.128, conflict-free
            float4 a1 = ea1[k4];
            float a0v[4] = {a0.x, a0.y, a0.z, a0.w};
            float a1v[4] = {a1.x, a1.y, a1.z, a1.w};
#pragma unroll
            for (int kk = 0; kk < 4; kk++) {
                unsigned long long A0 = pack2(a0v[kk]);
                unsigned long long A1 = pack2(a1v[kk]);
                const ulonglong2* w2 = reinterpret_cast<const ulonglong2*>(
                    &W1s[(k4 * 4 + kk) * HID + j0]);
#pragma unroll
                for (int m = 0; m < 8; m++) {
                    ulonglong2 w = w2[m];   // broadcast LDS.128
                    acc0[2*m]   = ffma2(A0, w.x, acc0[2*m]);
                    acc0[2*m+1] = ffma2(A0, w.y, acc0[2*m+1]);
                    acc1[2*m]   = ffma2(A1, w.x, acc1[2*m]);
                    acc1[2*m+1] = ffma2(A1, w.y, acc1[2*m+1]);
                }
            }
        }
#pragma unroll
        for (int m = 0; m < 16; m++) {
            U64F2 c0; c0.u = acc0[m];
            U64F2 c1; c1.u = acc1[m];
            float w2a = W2s[j0 + 2*m];
            float w2b = W2s[j0 + 2*m + 1];
            logit0 += fmaxf(c0.f.x, 0.f) * w2a + fmaxf(c0.f.y, 0.f) * w2b;
            logit1 += fmaxf(c1.f.x, 0.f) * w2a + fmaxf(c1.f.y, 0.f) * w2b;
        }
    }

    const int e0 = blockIdx.x * EPB + t;
    const int e1 = e0 + 128;
    {
        if (write_logits) logits[e0] = logit0;
        float ex = expf(logit0);
        g_exp[e0] = ex;
        int r = g_row[e0], c = g_col[e0];
        if (r < c)      atomicAdd(&g_sum_out[r], ex);
        else if (r > c) atomicAdd(&g_sum_in[r],  ex);
    }
    {
        if (write_logits) logits[e1] = logit1;
        float ex = expf(logit1);
        g_exp[e1] = ex;
        int r = g_row[e1], c = g_col[e1];
        if (r < c)      atomicAdd(&g_sum_out[r], ex);
        else if (r > c) atomicAdd(&g_sum_in[r],  ex);
    }
}

// ---------------------------------------------------------------------------
// Kernel 6: fused gather-aggregate + 1x1 conv. One block per node.
// ---------------------------------------------------------------------------
#define ECHUNK 128

__global__ void __launch_bounds__(256)
fused_kernel(const float* __restrict__ x,
             const float* __restrict__ Wn,
             const float* __restrict__ bn,
             float* __restrict__ out) {
    __shared__ float s_fo[CHW];      // flow_out
    __shared__ float s_fi[CHW];      // flow_in
    __shared__ float WsT[48 * 16];   // WsT[cc][o] = Wn[o*48+cc]
    __shared__ float bs[16];
    __shared__ int   s_ec[ECHUNK];
    __shared__ float s_ew[ECHUNK];

    const int n = blockIdx.x;
    const int t = threadIdx.x;

    for (int i = t; i < 768; i += 256) {
        int o = i / 48, cc = i % 48;
        WsT[cc * 16 + o] = Wn[i];
    }
    if (t < 16) bs[t] = bn[t];

    const int off0 = g_off[2 * n];
    const int off1 = g_off[2 * n + 1];
    const int off2 = g_off[2 * n + 2];

    const float invO = 1.f / fmaxf(g_sum_out[n], 1e-30f);
    const float invI = 1.f / fmaxf(g_sum_in[n],  1e-30f);

    const float4* x4 = reinterpret_cast<const float4*>(x);

    float4 accO = make_float4(0.f, 0.f, 0.f, 0.f);
    float4 accI = make_float4(0.f, 0.f, 0.f, 0.f);

    for (int base = off0; base < off1; base += ECHUNK) {
        int m = min(ECHUNK, off1 - base);
        __syncthreads();
        for (int j = t; j < m; j += 256) {
            s_ec[j] = g_scol[base + j];
            s_ew[j] = g_exp[g_eid[base + j]] * invO;
        }
        __syncthreads();
#pragma unroll 2
        for (int j = 0; j < m; j++) {
            float w = s_ew[j];
            float4 xv = __ldg(&x4[(size_t)s_ec[j] * 256 + t]);
            accO.x += w * xv.x; accO.y += w * xv.y;
            accO.z += w * xv.z; accO.w += w * xv.w;
        }
    }
    for (int base = off1; base < off2; base += ECHUNK) {
        int m = min(ECHUNK, off2 - base);
        __syncthreads();
        for (int j = t; j < m; j += 256) {
            s_ec[j] = g_scol[base + j];
            s_ew[j] = g_exp[g_eid[base + j]] * invI;
        }
        __syncthreads();
#pragma unroll 2
        for (int j = 0; j < m; j++) {
            float w = s_ew[j];
            float4 xv = __ldg(&x4[(size_t)s_ec[j] * 256 + t]);
            accI.x += w * xv.x; accI.y += w * xv.y;
            accI.z += w * xv.z; accI.w += w * xv.w;
        }
    }

    __syncthreads();
    reinterpret_cast<float4*>(s_fo)[t] = accO;
    reinterpret_cast<float4*>(s_fi)[t] = accI;
    __syncthreads();

    const int hw = t & 63;
    const int og = t >> 6;

    float acc[4];
#pragma unroll
    for (int j = 0; j < 4; j++) acc[j] = bs[og * 4 + j];

    const float* xb = x + (size_t)n * CHW;
#pragma unroll 4
    for (int cc = 0; cc < 16; cc++) {
        float vx = __ldg(&xb[cc * 64 + hw]);
        float vi = s_fi[cc * 64 + hw];
        float vo = s_fo[cc * 64 + hw];
        float4 wx = reinterpret_cast<const float4*>(&WsT[(cc)      * 16])[og];
        float4 wi = reinterpret_cast<const float4*>(&WsT[(16 + cc) * 16])[og];
        float4 wo = reinterpret_cast<const float4*>(&WsT[(32 + cc) * 16])[og];
        acc[0] += vx * wx.x + vi * wi.x + vo * wo.x;
        acc[1] += vx * wx.y + vi * wi.y + vo * wo.y;
        acc[2] += vx * wx.z + vi * wi.z + vo * wo.z;
        acc[3] += vx * wx.w + vi * wi.w + vo * wo.w;
    }

    float* ob = out + (size_t)n * CHW;
#pragma unroll
    for (int j = 0; j < 4; j++)
        ob[(og * 4 + j) * 64 + hw] = acc[j];
}

// ---------------------------------------------------------------------------
// Launch (default stream; sequentially ordered; graph-capturable)
// ---------------------------------------------------------------------------
extern "C" void kernel_launch(void* const* d_in, const int* in_sizes, int n_in,
                              void* d_out, int out_size) {
    const float* x         = (const float*)d_in[0];
    const float* edge_attr = (const float*)d_in[1];
    const float* W1        = (const float*)d_in[2];
    const float* b1        = (const float*)d_in[3];
    const float* W2        = (const float*)d_in[4];
    const float* b2        = (const float*)d_in[5];
    const float* Wn        = (const float*)d_in[6];
    const float* bn        = (const float*)d_in[7];
    const int*   ei32      = (const int*)d_in[8];

    float* out    = (float*)d_out;
    const int write_logits = (out_size >= NN * CHW + EE);
    float* logits = out + (size_t)NN * CHW;

    cudaFuncSetAttribute(mlp_kernel,
                         cudaFuncAttributeMaxDynamicSharedMemorySize,
                         MLP_SMEM_BYTES);

    const int EB = (EE + 255) / 256;

    zero_kernel<<<(NSEG + 255) / 256, 256>>>(ei32);
    decode_kernel<<<EB, 256>>>(ei32);
    scanA_kernel<<<NSCANB, 1024>>>();
    scanB_kernel<<<1, 32>>>();
    scanC_kernel<<<(NSEG + 255) / 256, 256>>>();
    fill_kernel<<<EB, 256>>>();
    mlp_kernel<<<EE / EPB, 128, MLP_SMEM_BYTES>>>(edge_attr, W1, b1, W2, b2,
                                                  logits, write_logits);
    fused_kernel<<<NN, 256>>>(x, Wn, bn, out);
}